// round 13
// baseline (speedup 1.0000x reference)
#include <cuda_runtime.h>
#include <cuda_bf16.h>

typedef unsigned int u32;
typedef unsigned long long u64;

#define EPSV 1e-5f
// 0.125 * log2(e): q pre-scale so softmax exp becomes exp2 (MUFU.EX2)
#define QSCALE 0.18033688011112042f

// ---- smem (per CTA, 25600B) ----
#define HB_OFF  0        // 8KB: LN out / attn out / LN2 out (bf16 swizzled)
#define KB_OFF  8192     // 8KB: k bf16 (relu buffer A in FFN)
#define VB_OFF  16384    // 8KB: v bf16 (relu buffer B in FFN)
#define LNP_OFF 24576    // 1KB: LN partial sums
#define SMEM_BYTES 25600

// weights in MMA B-fragment order:
// [tile(12)][nh(2)][kk(4)][half(2)][lane(32)] x uint4
// tile: 0-2 Wq/Wk/Wv, 3 Wo, 4-7 W1 chunks, 8-11 W2 chunks
__device__ __align__(16) unsigned char g_wfrag[98304];

__device__ __forceinline__ u32 swz(int row, int colbytes) {
    return (u32)(row * 128) + ((u32)colbytes ^ (u32)((row & 7) << 4));
}

__device__ __forceinline__ u32 smem_u32(const void* p) {
    u32 a;
    asm("{ .reg .u64 t; cvta.to.shared.u64 t, %1; cvt.u32.u64 %0, t; }"
        : "=r"(a) : "l"(p));
    return a;
}

__device__ __forceinline__ void ldsm_x4(u32 addr, u32& r0, u32& r1, u32& r2, u32& r3) {
    asm volatile("ldmatrix.sync.aligned.m8n8.x4.shared.b16 {%0,%1,%2,%3}, [%4];"
                 : "=r"(r0), "=r"(r1), "=r"(r2), "=r"(r3) : "r"(addr));
}
__device__ __forceinline__ void ldsm_x4t(u32 addr, u32& r0, u32& r1, u32& r2, u32& r3) {
    asm volatile("ldmatrix.sync.aligned.m8n8.x4.trans.shared.b16 {%0,%1,%2,%3}, [%4];"
                 : "=r"(r0), "=r"(r1), "=r"(r2), "=r"(r3) : "r"(addr));
}
__device__ __forceinline__ void mma_bf16(float* d, u32 a0, u32 a1, u32 a2, u32 a3,
                                         u32 b0, u32 b1) {
    asm volatile(
        "mma.sync.aligned.m16n8k16.row.col.f32.bf16.bf16.f32 "
        "{%0,%1,%2,%3}, {%4,%5,%6,%7}, {%8,%9}, {%0,%1,%2,%3};"
        : "+f"(d[0]), "+f"(d[1]), "+f"(d[2]), "+f"(d[3])
        : "r"(a0), "r"(a1), "r"(a2), "r"(a3), "r"(b0), "r"(b1));
}
__device__ __forceinline__ void mma_bf16_k8(float* d, u32 a0, u32 a1, u32 b0) {
    asm volatile(
        "mma.sync.aligned.m16n8k8.row.col.f32.bf16.bf16.f32 "
        "{%0,%1,%2,%3}, {%4,%5}, {%6}, {%0,%1,%2,%3};"
        : "+f"(d[0]), "+f"(d[1]), "+f"(d[2]), "+f"(d[3])
        : "r"(a0), "r"(a1), "r"(b0));
}

__device__ __forceinline__ void load_afrags(u32 abase, int m0, u32 af[4][4]) {
    const int l = threadIdx.x & 31;
    const int ar = m0 + (l & 15);
    const u32 arow = abase + (u32)(ar * 128);
    const u32 axor = (u32)((ar & 7) << 4);
    const int acol = (l >> 4) * 8;
    #pragma unroll
    for (int kk = 0; kk < 4; kk++)
        ldsm_x4(arow + (((u32)((kk * 16 + acol) * 2)) ^ axor),
                af[kk][0], af[kk][1], af[kk][2], af[kk][3]);
}

// D[16x32] += A(frags) * B[64x64] (cols nh*32..+31); B frags via coalesced LDG (L1-hit)
__device__ __forceinline__ void gemm64_frag(const u32 af[4][4],
                                            const uint4* __restrict__ wf, float d[16]) {
    const int l = threadIdx.x & 31;
    #pragma unroll
    for (int kk = 0; kk < 4; kk++) {
        uint4 B0 = __ldg(&wf[kk * 64 + l]);
        uint4 B1 = __ldg(&wf[kk * 64 + 32 + l]);
        mma_bf16(d + 0, af[kk][0], af[kk][1], af[kk][2], af[kk][3], B0.x, B0.y);
        mma_bf16(d + 4, af[kk][0], af[kk][1], af[kk][2], af[kk][3], B0.z, B0.w);
        mma_bf16(d + 8, af[kk][0], af[kk][1], af[kk][2], af[kk][3], B1.x, B1.y);
        mma_bf16(d + 12, af[kk][0], af[kk][1], af[kk][2], af[kk][3], B1.z, B1.w);
    }
}

__device__ __forceinline__ void gemm64g(u32 abase, int m0,
                                        const uint4* __restrict__ wf, float d[16]) {
    u32 af[4][4];
    load_afrags(abase, m0, af);
    gemm64_frag(af, wf, d);
}

__device__ __forceinline__ u32 packbf2(float a, float b) {
    __nv_bfloat162 p = __float22bfloat162_rn(make_float2(a, b));
    return *(u32*)&p;
}

__device__ __forceinline__ void store_bf16_tile(unsigned char* t, int m0, int nh,
                                                const float d[16]) {
    const int l = threadIdx.x & 31;
    const int grp = l >> 2, tig = l & 3;
    const int r0 = m0 + grp, r1 = m0 + grp + 8;
    #pragma unroll
    for (int nb = 0; nb < 4; nb++) {
        int cb = (nh * 32 + nb * 8 + tig * 2) * 2;
        *(u32*)(t + swz(r0, cb)) = packbf2(d[nb * 4 + 0], d[nb * 4 + 1]);
        *(u32*)(t + swz(r1, cb)) = packbf2(d[nb * 4 + 2], d[nb * 4 + 3]);
    }
}

// fragment-layout LayerNorm: xv[16] -> bf16 HB tile. ONE internal __syncthreads
// (doubles as WAR barrier for overwriting hb after its previous readers finish).
__device__ __forceinline__ void ln_frag(const float xv[16], unsigned char* hb,
                                        float* lnp, const float* g, const float* be,
                                        int m0, int nh, int l) {
    const int grp = l >> 2, tig = l & 3;
    const int r0 = m0 + grp, r1 = r0 + 8;
    float s0 = 0.f, ss0 = 0.f, s1 = 0.f, ss1 = 0.f;
    #pragma unroll
    for (int nb = 0; nb < 4; nb++) {
        s0 += xv[nb * 4 + 0] + xv[nb * 4 + 1];
        ss0 += xv[nb * 4 + 0] * xv[nb * 4 + 0] + xv[nb * 4 + 1] * xv[nb * 4 + 1];
        s1 += xv[nb * 4 + 2] + xv[nb * 4 + 3];
        ss1 += xv[nb * 4 + 2] * xv[nb * 4 + 2] + xv[nb * 4 + 3] * xv[nb * 4 + 3];
    }
    s0 += __shfl_xor_sync(0xffffffffu, s0, 1);
    s0 += __shfl_xor_sync(0xffffffffu, s0, 2);
    ss0 += __shfl_xor_sync(0xffffffffu, ss0, 1);
    ss0 += __shfl_xor_sync(0xffffffffu, ss0, 2);
    s1 += __shfl_xor_sync(0xffffffffu, s1, 1);
    s1 += __shfl_xor_sync(0xffffffffu, s1, 2);
    ss1 += __shfl_xor_sync(0xffffffffu, ss1, 1);
    ss1 += __shfl_xor_sync(0xffffffffu, ss1, 2);
    if (tig == 0) {
        *(float2*)&lnp[(nh * 64 + r0) * 2] = make_float2(s0, ss0);
        *(float2*)&lnp[(nh * 64 + r1) * 2] = make_float2(s1, ss1);
    }
    __syncthreads();
    float2 p0 = *(float2*)&lnp[((1 - nh) * 64 + r0) * 2];
    float2 p1 = *(float2*)&lnp[((1 - nh) * 64 + r1) * 2];
    float S0 = s0 + p0.x, Q0 = ss0 + p0.y;
    float S1 = s1 + p1.x, Q1 = ss1 + p1.y;
    float mu0 = S0 * (1.0f / 64.0f);
    float rs0 = rsqrtf(Q0 * (1.0f / 64.0f) - mu0 * mu0 + EPSV);
    float mu1 = S1 * (1.0f / 64.0f);
    float rs1 = rsqrtf(Q1 * (1.0f / 64.0f) - mu1 * mu1 + EPSV);
    #pragma unroll
    for (int nb = 0; nb < 4; nb++) {
        int col = nh * 32 + nb * 8 + tig * 2;
        float2 gv = *(const float2*)&g[col];
        float2 bv = *(const float2*)&be[col];
        float a0 = (xv[nb * 4 + 0] - mu0) * rs0 * gv.x + bv.x;
        float a1 = (xv[nb * 4 + 1] - mu0) * rs0 * gv.y + bv.y;
        float c0 = (xv[nb * 4 + 2] - mu1) * rs1 * gv.x + bv.x;
        float c1 = (xv[nb * 4 + 3] - mu1) * rs1 * gv.y + bv.y;
        *(u32*)(hb + swz(r0, col * 2)) = packbf2(a0, a1);
        *(u32*)(hb + swz(r1, col * 2)) = packbf2(c0, c1);
    }
}

// ---------------- prep: weights -> bf16 B-fragment order ----------------
__device__ __forceinline__ float w_fetch(int tile, int k, int n,
                                         const float* Wq, const float* Wk,
                                         const float* Wv, const float* Wo,
                                         const float* W1, const float* W2) {
    if (tile < 3) {
        const float* s = (tile == 0) ? Wq : (tile == 1) ? Wk : Wv;
        return s[k * 64 + n];
    } else if (tile == 3) {
        return Wo[k * 64 + n];
    } else if (tile < 8) {
        return W1[k * 256 + (tile - 4) * 64 + n];
    }
    return W2[((tile - 8) * 64 + k) * 64 + n];
}

__global__ void prep_kernel(const float* __restrict__ Wq, const float* __restrict__ Wk,
                            const float* __restrict__ Wv, const float* __restrict__ Wo,
                            const float* __restrict__ W1, const float* __restrict__ W2) {
    const int tile = blockIdx.x;
    for (int idx = threadIdx.x; idx < 2048; idx += 256) {
        int nh = idx >> 10;
        int rem = idx & 1023;
        int kk = rem >> 8;
        int rem2 = rem & 255;
        int half = rem2 >> 7;
        int rem3 = rem2 & 127;
        int lane = rem3 >> 2, i = rem3 & 3;
        int nblk = half * 2 + (i >> 1), hi = i & 1;
        int k = kk * 16 + (lane & 3) * 2 + hi * 8;
        int n = nh * 32 + nblk * 8 + (lane >> 2);
        float v0 = w_fetch(tile, k, n, Wq, Wk, Wv, Wo, W1, W2);
        float v1 = w_fetch(tile, k + 1, n, Wq, Wk, Wv, Wo, W1, W2);
        __nv_bfloat162 p = __float22bfloat162_rn(make_float2(v0, v1));
        *(u32*)(g_wfrag + tile * 8192 + nh * 4096 + kk * 1024 + half * 512 +
                lane * 16 + i * 4) = *(u32*)&p;
    }
}

__global__ void __launch_bounds__(256, 4)
block_kernel(const float* __restrict__ x,
             const float* __restrict__ bo,
             const float* __restrict__ b1, const float* __restrict__ b2,
             const float* __restrict__ g1, const float* __restrict__ be1,
             const float* __restrict__ g2, const float* __restrict__ be2,
             float* __restrict__ out) {
    extern __shared__ __align__(128) unsigned char smp[];
    float* lnp = (float*)(smp + LNP_OFF);
    const u32 sb = smem_u32(smp);

    const int tid = threadIdx.x;
    const int w = tid >> 5, l = tid & 31;
    const float* xg = x + (size_t)blockIdx.x * 4096;
    float* og = out + (size_t)blockIdx.x * 4096;

    const int strip = w & 3;       // 16-row strip index
    const int m0 = strip * 16;
    const int nh = w >> 2;         // 32-col half (0/1) == head-group
    const int grp = l >> 2, tig = l & 3;
    const int r0 = m0 + grp, r1 = r0 + 8;
    const uint4* wbase = (const uint4*)(g_wfrag + nh * 4096);

    // ---- LN1 (xv NOT kept live past this phase; x reloaded later) ----
    {
        float xv[16];
        #pragma unroll
        for (int nb = 0; nb < 4; nb++) {
            int col = nh * 32 + nb * 8 + tig * 2;
            float2 t0 = *(const float2*)&xg[r0 * 64 + col];
            float2 t1 = *(const float2*)&xg[r1 * 64 + col];
            xv[nb * 4 + 0] = t0.x; xv[nb * 4 + 1] = t0.y;
            xv[nb * 4 + 2] = t1.x; xv[nb * 4 + 3] = t1.y;
        }
        ln_frag(xv, smp + HB_OFF, lnp, g1, be1, m0, nh, l);
    }
    __syncthreads();

    // ---- QKV: q kept in registers as m16k8 A-frags (exp2-prescaled); k/v -> smem ----
    u32 qa[4][2];
    {
        u32 af[4][4];
        load_afrags(sb + HB_OFF, m0, af);
        {
            float d[16] = {0};
            gemm64_frag(af, wbase + 0 * 512, d);
            #pragma unroll
            for (int j = 0; j < 4; j++) {
                qa[j][0] = packbf2(d[j * 4 + 0] * QSCALE, d[j * 4 + 1] * QSCALE);
                qa[j][1] = packbf2(d[j * 4 + 2] * QSCALE, d[j * 4 + 3] * QSCALE);
            }
        }
        {
            float d[16] = {0};
            gemm64_frag(af, wbase + 1 * 512, d);
            store_bf16_tile(smp + KB_OFF, m0, nh, d);
        }
        {
            float d[16] = {0};
            gemm64_frag(af, wbase + 2 * 512, d);
            store_bf16_tile(smp + VB_OFF, m0, nh, d);
        }
    }
    __syncthreads();

    // ---- attention (causal-block-skipped): warp = strip x heads nh*4..+3 ----
    {
        #pragma unroll
        for (int j = 0; j < 4; j++) {
            const int hcb = (nh * 4 + j) * 16;
            u32 kf[8], vf[8];
            ldsm_x4(sb + KB_OFF + swz(l, hcb), kf[0], kf[1], kf[2], kf[3]);
            ldsm_x4t(sb + VB_OFF + swz(l, hcb), vf[0], vf[1], vf[2], vf[3]);
            if (strip >= 2) {
                ldsm_x4(sb + KB_OFF + swz(32 + l, hcb), kf[4], kf[5], kf[6], kf[7]);
                ldsm_x4t(sb + VB_OFF + swz(32 + l, hcb), vf[4], vf[5], vf[6], vf[7]);
            }

            u32 pa[8], pb[8];
            float sum0 = 0.f, sum1 = 0.f;
            #pragma unroll
            for (int nb = 0; nb < 8; nb++) {
                if (nb >= 2 * strip + 2) continue;  // fully-masked block: skip
                float sacc[4] = {0.f, 0.f, 0.f, 0.f};
                mma_bf16_k8(sacc, qa[j][0], qa[j][1], kf[nb]);
                float e0, e1, e2, e3;
                if (nb < 2 * strip) {               // fully-unmasked: no compares
                    e0 = exp2f(sacc[0]); e1 = exp2f(sacc[1]);
                    e2 = exp2f(sacc[2]); e3 = exp2f(sacc[3]);
                } else {                            // boundary block
                    const int c0 = nb * 8 + 2 * tig;
                    e0 = (c0     <= r0    ) ? exp2f(sacc[0]) : 0.f;
                    e1 = (c0 + 1 <= r0    ) ? exp2f(sacc[1]) : 0.f;
                    e2 = (c0     <= r0 + 8) ? exp2f(sacc[2]) : 0.f;
                    e3 = (c0 + 1 <= r0 + 8) ? exp2f(sacc[3]) : 0.f;
                }
                sum0 += e0 + e1;
                sum1 += e2 + e3;
                pa[nb] = packbf2(e0, e1);
                pb[nb] = packbf2(e2, e3);
            }
            sum0 += __shfl_xor_sync(0xffffffffu, sum0, 1);
            sum0 += __shfl_xor_sync(0xffffffffu, sum0, 2);
            sum1 += __shfl_xor_sync(0xffffffffu, sum1, 1);
            sum1 += __shfl_xor_sync(0xffffffffu, sum1, 2);
            const float inv0 = 1.0f / sum0, inv1 = 1.0f / sum1;

            float o[4] = {0.f, 0.f, 0.f, 0.f};
            #pragma unroll
            for (int kb = 0; kb < 4; kb++)
                if (kb <= strip)
                    mma_bf16(o, pa[2 * kb], pb[2 * kb], pa[2 * kb + 1], pb[2 * kb + 1],
                             vf[2 * kb], vf[2 * kb + 1]);
            *(u32*)(smp + HB_OFF + swz(r0, hcb + 4 * tig)) =
                packbf2(o[0] * inv0, o[1] * inv0);
            *(u32*)(smp + HB_OFF + swz(r1, hcb + 4 * tig)) =
                packbf2(o[2] * inv1, o[3] * inv1);
        }
    }
    __syncthreads();

    // ---- Wo GEMM; x1 = x(reloaded) + attn@Wo + bo ----
    float xv[16];
    {
        float d[16] = {0};
        gemm64g(sb + HB_OFF, m0, wbase + 3 * 512, d);
        #pragma unroll
        for (int nb = 0; nb < 4; nb++) {
            int col = nh * 32 + nb * 8 + tig * 2;
            float2 bv = *(const float2*)&bo[col];
            float2 t0 = *(const float2*)&xg[r0 * 64 + col];
            float2 t1 = *(const float2*)&xg[r1 * 64 + col];
            xv[nb * 4 + 0] = t0.x + d[nb * 4 + 0] + bv.x;
            xv[nb * 4 + 1] = t0.y + d[nb * 4 + 1] + bv.y;
            xv[nb * 4 + 2] = t1.x + d[nb * 4 + 2] + bv.x;
            xv[nb * 4 + 3] = t1.y + d[nb * 4 + 3] + bv.y;
        }
    }
    // LN2 -> HB (internal sync orders HB attn-reads before overwrite)
    ln_frag(xv, smp + HB_OFF, lnp, g2, be2, m0, nh, l);
    __syncthreads();

    // ---- FFN: HB A-frags loaded once; relu double-buffered KB/VB (1 sync/chunk) ----
    float dff[16] = {0};
    {
        u32 af2[4][4];
        load_afrags(sb + HB_OFF, m0, af2);
        #pragma unroll
        for (int c = 0; c < 4; c++) {
            const u32 rbo = (c & 1) ? (u32)VB_OFF : (u32)KB_OFF;
            {
                float d[16] = {0};
                gemm64_frag(af2, wbase + (4 + c) * 512, d);
                #pragma unroll
                for (int nb = 0; nb < 4; nb++) {
                    int col = nh * 32 + nb * 8 + tig * 2;
                    float2 bv = *(const float2*)&b1[c * 64 + col];
                    u32 p0 = packbf2(fmaxf(d[nb * 4 + 0] + bv.x, 0.f),
                                     fmaxf(d[nb * 4 + 1] + bv.y, 0.f));
                    u32 p1 = packbf2(fmaxf(d[nb * 4 + 2] + bv.x, 0.f),
                                     fmaxf(d[nb * 4 + 3] + bv.y, 0.f));
                    *(u32*)(smp + rbo + swz(r0, col * 2)) = p0;
                    *(u32*)(smp + rbo + swz(r1, col * 2)) = p1;
                }
            }
            __syncthreads();
            gemm64g(sb + rbo, m0, wbase + (8 + c) * 512, dff);
            // no trailing sync: next chunk writes the OTHER buffer; its sync
            // orders re-writes of this buffer (c+2) after all readers.
        }
    }

    // ---- out = x1 + ff + b2 (registers -> global) ----
    #pragma unroll
    for (int nb = 0; nb < 4; nb++) {
        int col = nh * 32 + nb * 8 + tig * 2;
        float2 bv = *(const float2*)&b2[col];
        float2 o0 = {xv[nb * 4 + 0] + dff[nb * 4 + 0] + bv.x,
                     xv[nb * 4 + 1] + dff[nb * 4 + 1] + bv.y};
        float2 o1 = {xv[nb * 4 + 2] + dff[nb * 4 + 2] + bv.x,
                     xv[nb * 4 + 3] + dff[nb * 4 + 3] + bv.y};
        *(float2*)&og[r0 * 64 + col] = o0;
        *(float2*)&og[r1 * 64 + col] = o1;
    }
}

extern "C" void kernel_launch(void* const* d_in, const int* in_sizes, int n_in,
                              void* d_out, int out_size) {
    (void)in_sizes; (void)n_in; (void)out_size;
    const float* x   = (const float*)d_in[0];
    const float* Wq  = (const float*)d_in[1];
    const float* Wk  = (const float*)d_in[2];
    const float* Wv  = (const float*)d_in[3];
    const float* Wo  = (const float*)d_in[4];
    const float* bo  = (const float*)d_in[5];
    const float* W1  = (const float*)d_in[6];
    const float* b1  = (const float*)d_in[7];
    const float* W2  = (const float*)d_in[8];
    const float* b2  = (const float*)d_in[9];
    const float* g1  = (const float*)d_in[10];
    const float* be1 = (const float*)d_in[11];
    const float* g2  = (const float*)d_in[12];
    const float* be2 = (const float*)d_in[13];
    float* out = (float*)d_out;

    prep_kernel<<<12, 256>>>(Wq, Wk, Wv, Wo, W1, W2);

    cudaFuncSetAttribute(block_kernel,
                         cudaFuncAttributeMaxDynamicSharedMemorySize, SMEM_BYTES);
    block_kernel<<<4096, 256, SMEM_BYTES>>>(x, bo, b1, b2, g1, be1, g2, be2, out);
}

// round 14
// speedup vs baseline: 1.0469x; 1.0469x over previous
#include <cuda_runtime.h>
#include <cuda_bf16.h>

typedef unsigned int u32;
typedef unsigned long long u64;

#define EPSV 1e-5f
// 0.125 * log2(e): q pre-scale so softmax exp becomes exp2 (MUFU.EX2)
#define QSCALE 0.18033688011112042f

// ---- smem (per CTA, 25600B) ----
#define HB_OFF  0        // 8KB: LN out / attn out / LN2 out (bf16 swizzled)
#define KB_OFF  8192     // 8KB: k bf16 (relu buffer A in FFN)
#define VB_OFF  16384    // 8KB: v bf16 (relu buffer B in FFN)
#define LNP_OFF 24576    // 1KB: LN partial sums
#define SMEM_BYTES 25600

// pair barrier: the two warps (strip, nh=0) and (strip, nh=1); 64 threads
#define PAIRBAR(s) asm volatile("bar.sync %0, 64;" :: "r"((s) + 1) : "memory")

// weights in MMA B-fragment order:
// [tile(12)][nh(2)][kk(4)][half(2)][lane(32)] x uint4
// tile: 0-2 Wq/Wk/Wv, 3 Wo, 4-7 W1 chunks, 8-11 W2 chunks
__device__ __align__(16) unsigned char g_wfrag[98304];

__device__ __forceinline__ u32 swz(int row, int colbytes) {
    return (u32)(row * 128) + ((u32)colbytes ^ (u32)((row & 7) << 4));
}

__device__ __forceinline__ u32 smem_u32(const void* p) {
    u32 a;
    asm("{ .reg .u64 t; cvta.to.shared.u64 t, %1; cvt.u32.u64 %0, t; }"
        : "=r"(a) : "l"(p));
    return a;
}

__device__ __forceinline__ void ldsm_x4(u32 addr, u32& r0, u32& r1, u32& r2, u32& r3) {
    asm volatile("ldmatrix.sync.aligned.m8n8.x4.shared.b16 {%0,%1,%2,%3}, [%4];"
                 : "=r"(r0), "=r"(r1), "=r"(r2), "=r"(r3) : "r"(addr));
}
__device__ __forceinline__ void ldsm_x4t(u32 addr, u32& r0, u32& r1, u32& r2, u32& r3) {
    asm volatile("ldmatrix.sync.aligned.m8n8.x4.trans.shared.b16 {%0,%1,%2,%3}, [%4];"
                 : "=r"(r0), "=r"(r1), "=r"(r2), "=r"(r3) : "r"(addr));
}
__device__ __forceinline__ void mma_bf16(float* d, u32 a0, u32 a1, u32 a2, u32 a3,
                                         u32 b0, u32 b1) {
    asm volatile(
        "mma.sync.aligned.m16n8k16.row.col.f32.bf16.bf16.f32 "
        "{%0,%1,%2,%3}, {%4,%5,%6,%7}, {%8,%9}, {%0,%1,%2,%3};"
        : "+f"(d[0]), "+f"(d[1]), "+f"(d[2]), "+f"(d[3])
        : "r"(a0), "r"(a1), "r"(a2), "r"(a3), "r"(b0), "r"(b1));
}
__device__ __forceinline__ void mma_bf16_k8(float* d, u32 a0, u32 a1, u32 b0) {
    asm volatile(
        "mma.sync.aligned.m16n8k8.row.col.f32.bf16.bf16.f32 "
        "{%0,%1,%2,%3}, {%4,%5}, {%6}, {%0,%1,%2,%3};"
        : "+f"(d[0]), "+f"(d[1]), "+f"(d[2]), "+f"(d[3])
        : "r"(a0), "r"(a1), "r"(b0));
}

__device__ __forceinline__ void load_afrags(u32 abase, int m0, u32 af[4][4]) {
    const int l = threadIdx.x & 31;
    const int ar = m0 + (l & 15);
    const u32 arow = abase + (u32)(ar * 128);
    const u32 axor = (u32)((ar & 7) << 4);
    const int acol = (l >> 4) * 8;
    #pragma unroll
    for (int kk = 0; kk < 4; kk++)
        ldsm_x4(arow + (((u32)((kk * 16 + acol) * 2)) ^ axor),
                af[kk][0], af[kk][1], af[kk][2], af[kk][3]);
}

// D[16x32] += A(frags) * B[64x64] (cols nh*32..+31); B frags via coalesced LDG (L1-hit)
__device__ __forceinline__ void gemm64_frag(const u32 af[4][4],
                                            const uint4* __restrict__ wf, float d[16]) {
    const int l = threadIdx.x & 31;
    #pragma unroll
    for (int kk = 0; kk < 4; kk++) {
        uint4 B0 = __ldg(&wf[kk * 64 + l]);
        uint4 B1 = __ldg(&wf[kk * 64 + 32 + l]);
        mma_bf16(d + 0, af[kk][0], af[kk][1], af[kk][2], af[kk][3], B0.x, B0.y);
        mma_bf16(d + 4, af[kk][0], af[kk][1], af[kk][2], af[kk][3], B0.z, B0.w);
        mma_bf16(d + 8, af[kk][0], af[kk][1], af[kk][2], af[kk][3], B1.x, B1.y);
        mma_bf16(d + 12, af[kk][0], af[kk][1], af[kk][2], af[kk][3], B1.z, B1.w);
    }
}

__device__ __forceinline__ void gemm64g(u32 abase, int m0,
                                        const uint4* __restrict__ wf, float d[16]) {
    u32 af[4][4];
    load_afrags(abase, m0, af);
    gemm64_frag(af, wf, d);
}

__device__ __forceinline__ u32 packbf2(float a, float b) {
    __nv_bfloat162 p = __float22bfloat162_rn(make_float2(a, b));
    return *(u32*)&p;
}

__device__ __forceinline__ void store_bf16_tile(unsigned char* t, int m0, int nh,
                                                const float d[16]) {
    const int l = threadIdx.x & 31;
    const int grp = l >> 2, tig = l & 3;
    const int r0 = m0 + grp, r1 = m0 + grp + 8;
    #pragma unroll
    for (int nb = 0; nb < 4; nb++) {
        int cb = (nh * 32 + nb * 8 + tig * 2) * 2;
        *(u32*)(t + swz(r0, cb)) = packbf2(d[nb * 4 + 0], d[nb * 4 + 1]);
        *(u32*)(t + swz(r1, cb)) = packbf2(d[nb * 4 + 2], d[nb * 4 + 3]);
    }
}

// fragment-layout LayerNorm: xv[16] -> bf16 HB tile.
// Internal PAIR barrier: the row sums only couple the two warps of one strip.
__device__ __forceinline__ void ln_frag(const float xv[16], unsigned char* hb,
                                        float* lnp, const float* g, const float* be,
                                        int m0, int nh, int l, int strip) {
    const int grp = l >> 2, tig = l & 3;
    const int r0 = m0 + grp, r1 = r0 + 8;
    float s0 = 0.f, ss0 = 0.f, s1 = 0.f, ss1 = 0.f;
    #pragma unroll
    for (int nb = 0; nb < 4; nb++) {
        s0 += xv[nb * 4 + 0] + xv[nb * 4 + 1];
        ss0 += xv[nb * 4 + 0] * xv[nb * 4 + 0] + xv[nb * 4 + 1] * xv[nb * 4 + 1];
        s1 += xv[nb * 4 + 2] + xv[nb * 4 + 3];
        ss1 += xv[nb * 4 + 2] * xv[nb * 4 + 2] + xv[nb * 4 + 3] * xv[nb * 4 + 3];
    }
    s0 += __shfl_xor_sync(0xffffffffu, s0, 1);
    s0 += __shfl_xor_sync(0xffffffffu, s0, 2);
    ss0 += __shfl_xor_sync(0xffffffffu, ss0, 1);
    ss0 += __shfl_xor_sync(0xffffffffu, ss0, 2);
    s1 += __shfl_xor_sync(0xffffffffu, s1, 1);
    s1 += __shfl_xor_sync(0xffffffffu, s1, 2);
    ss1 += __shfl_xor_sync(0xffffffffu, ss1, 1);
    ss1 += __shfl_xor_sync(0xffffffffu, ss1, 2);
    if (tig == 0) {
        *(float2*)&lnp[(nh * 64 + r0) * 2] = make_float2(s0, ss0);
        *(float2*)&lnp[(nh * 64 + r1) * 2] = make_float2(s1, ss1);
    }
    PAIRBAR(strip);
    float2 p0 = *(float2*)&lnp[((1 - nh) * 64 + r0) * 2];
    float2 p1 = *(float2*)&lnp[((1 - nh) * 64 + r1) * 2];
    float S0 = s0 + p0.x, Q0 = ss0 + p0.y;
    float S1 = s1 + p1.x, Q1 = ss1 + p1.y;
    float mu0 = S0 * (1.0f / 64.0f);
    float rs0 = rsqrtf(Q0 * (1.0f / 64.0f) - mu0 * mu0 + EPSV);
    float mu1 = S1 * (1.0f / 64.0f);
    float rs1 = rsqrtf(Q1 * (1.0f / 64.0f) - mu1 * mu1 + EPSV);
    #pragma unroll
    for (int nb = 0; nb < 4; nb++) {
        int col = nh * 32 + nb * 8 + tig * 2;
        float2 gv = *(const float2*)&g[col];
        float2 bv = *(const float2*)&be[col];
        float a0 = (xv[nb * 4 + 0] - mu0) * rs0 * gv.x + bv.x;
        float a1 = (xv[nb * 4 + 1] - mu0) * rs0 * gv.y + bv.y;
        float c0 = (xv[nb * 4 + 2] - mu1) * rs1 * gv.x + bv.x;
        float c1 = (xv[nb * 4 + 3] - mu1) * rs1 * gv.y + bv.y;
        *(u32*)(hb + swz(r0, col * 2)) = packbf2(a0, a1);
        *(u32*)(hb + swz(r1, col * 2)) = packbf2(c0, c1);
    }
}

// ---------------- prep: weights -> bf16 B-fragment order ----------------
__device__ __forceinline__ float w_fetch(int tile, int k, int n,
                                         const float* Wq, const float* Wk,
                                         const float* Wv, const float* Wo,
                                         const float* W1, const float* W2) {
    if (tile < 3) {
        const float* s = (tile == 0) ? Wq : (tile == 1) ? Wk : Wv;
        return s[k * 64 + n];
    } else if (tile == 3) {
        return Wo[k * 64 + n];
    } else if (tile < 8) {
        return W1[k * 256 + (tile - 4) * 64 + n];
    }
    return W2[((tile - 8) * 64 + k) * 64 + n];
}

__global__ void prep_kernel(const float* __restrict__ Wq, const float* __restrict__ Wk,
                            const float* __restrict__ Wv, const float* __restrict__ Wo,
                            const float* __restrict__ W1, const float* __restrict__ W2) {
    const int tile = blockIdx.x;
    for (int idx = threadIdx.x; idx < 2048; idx += 256) {
        int nh = idx >> 10;
        int rem = idx & 1023;
        int kk = rem >> 8;
        int rem2 = rem & 255;
        int half = rem2 >> 7;
        int rem3 = rem2 & 127;
        int lane = rem3 >> 2, i = rem3 & 3;
        int nblk = half * 2 + (i >> 1), hi = i & 1;
        int k = kk * 16 + (lane & 3) * 2 + hi * 8;
        int n = nh * 32 + nblk * 8 + (lane >> 2);
        float v0 = w_fetch(tile, k, n, Wq, Wk, Wv, Wo, W1, W2);
        float v1 = w_fetch(tile, k + 1, n, Wq, Wk, Wv, Wo, W1, W2);
        __nv_bfloat162 p = __float22bfloat162_rn(make_float2(v0, v1));
        *(u32*)(g_wfrag + tile * 8192 + nh * 4096 + kk * 1024 + half * 512 +
                lane * 16 + i * 4) = *(u32*)&p;
    }
}

__global__ void __launch_bounds__(256, 3)
block_kernel(const float* __restrict__ x,
             const float* __restrict__ bo,
             const float* __restrict__ b1, const float* __restrict__ b2,
             const float* __restrict__ g1, const float* __restrict__ be1,
             const float* __restrict__ g2, const float* __restrict__ be2,
             float* __restrict__ out) {
    extern __shared__ __align__(128) unsigned char smp[];
    float* lnp = (float*)(smp + LNP_OFF);
    const u32 sb = smem_u32(smp);

    const int tid = threadIdx.x;
    const int w = tid >> 5, l = tid & 31;
    const float* xg = x + (size_t)blockIdx.x * 4096;
    float* og = out + (size_t)blockIdx.x * 4096;

    const int strip = w & 3;       // 16-row strip index
    const int m0 = strip * 16;
    const int nh = w >> 2;         // 32-col half (0/1) == head-group
    const int grp = l >> 2, tig = l & 3;
    const int r0 = m0 + grp, r1 = r0 + 8;
    const uint4* wbase = (const uint4*)(g_wfrag + nh * 4096);

    // ---- load x residual (kept live all kernel); LN1 -> HB ----
    float xv[16];
    #pragma unroll
    for (int nb = 0; nb < 4; nb++) {
        int col = nh * 32 + nb * 8 + tig * 2;
        float2 t0 = *(const float2*)&xg[r0 * 64 + col];
        float2 t1 = *(const float2*)&xg[r1 * 64 + col];
        xv[nb * 4 + 0] = t0.x; xv[nb * 4 + 1] = t0.y;
        xv[nb * 4 + 2] = t1.x; xv[nb * 4 + 3] = t1.y;
    }
    ln_frag(xv, smp + HB_OFF, lnp, g1, be1, m0, nh, l, strip);
    PAIRBAR(strip);   // HB strip rows visible to the pair

    // ---- QKV: q kept in registers as m16k8 A-frags (exp2-prescaled); k/v -> smem ----
    u32 qa[4][2];
    {
        u32 af[4][4];
        load_afrags(sb + HB_OFF, m0, af);  // reads HB rows of own strip only
        {
            float d[16] = {0};
            gemm64_frag(af, wbase + 0 * 512, d);
            #pragma unroll
            for (int j = 0; j < 4; j++) {
                qa[j][0] = packbf2(d[j * 4 + 0] * QSCALE, d[j * 4 + 1] * QSCALE);
                qa[j][1] = packbf2(d[j * 4 + 2] * QSCALE, d[j * 4 + 3] * QSCALE);
            }
        }
        {
            float d[16] = {0};
            gemm64_frag(af, wbase + 1 * 512, d);
            store_bf16_tile(smp + KB_OFF, m0, nh, d);
        }
        {
            float d[16] = {0};
            gemm64_frag(af, wbase + 2 * 512, d);
            store_bf16_tile(smp + VB_OFF, m0, nh, d);
        }
    }
    __syncthreads();  // FULL: attention reads K/V rows from ALL strips

    // ---- attention (causal-block-skipped): warp = strip x heads nh*4..+3 ----
    {
        #pragma unroll
        for (int j = 0; j < 4; j++) {
            const int hcb = (nh * 4 + j) * 16;
            u32 kf[8], vf[8];
            ldsm_x4(sb + KB_OFF + swz(l, hcb), kf[0], kf[1], kf[2], kf[3]);
            ldsm_x4t(sb + VB_OFF + swz(l, hcb), vf[0], vf[1], vf[2], vf[3]);
            if (strip >= 2) {
                ldsm_x4(sb + KB_OFF + swz(32 + l, hcb), kf[4], kf[5], kf[6], kf[7]);
                ldsm_x4t(sb + VB_OFF + swz(32 + l, hcb), vf[4], vf[5], vf[6], vf[7]);
            }

            u32 pa[8], pb[8];
            float sum0 = 0.f, sum1 = 0.f;
            #pragma unroll
            for (int nb = 0; nb < 8; nb++) {
                if (nb >= 2 * strip + 2) continue;  // fully-masked block: skip
                float sacc[4] = {0.f, 0.f, 0.f, 0.f};
                mma_bf16_k8(sacc, qa[j][0], qa[j][1], kf[nb]);
                float e0, e1, e2, e3;
                if (nb < 2 * strip) {               // fully-unmasked: no compares
                    e0 = exp2f(sacc[0]); e1 = exp2f(sacc[1]);
                    e2 = exp2f(sacc[2]); e3 = exp2f(sacc[3]);
                } else {                            // boundary block
                    const int c0 = nb * 8 + 2 * tig;
                    e0 = (c0     <= r0    ) ? exp2f(sacc[0]) : 0.f;
                    e1 = (c0 + 1 <= r0    ) ? exp2f(sacc[1]) : 0.f;
                    e2 = (c0     <= r0 + 8) ? exp2f(sacc[2]) : 0.f;
                    e3 = (c0 + 1 <= r0 + 8) ? exp2f(sacc[3]) : 0.f;
                }
                sum0 += e0 + e1;
                sum1 += e2 + e3;
                pa[nb] = packbf2(e0, e1);
                pb[nb] = packbf2(e2, e3);
            }
            sum0 += __shfl_xor_sync(0xffffffffu, sum0, 1);
            sum0 += __shfl_xor_sync(0xffffffffu, sum0, 2);
            sum1 += __shfl_xor_sync(0xffffffffu, sum1, 1);
            sum1 += __shfl_xor_sync(0xffffffffu, sum1, 2);
            const float inv0 = 1.0f / sum0, inv1 = 1.0f / sum1;

            float o[4] = {0.f, 0.f, 0.f, 0.f};
            #pragma unroll
            for (int kb = 0; kb < 4; kb++)
                if (kb <= strip)
                    mma_bf16(o, pa[2 * kb], pb[2 * kb], pa[2 * kb + 1], pb[2 * kb + 1],
                             vf[2 * kb], vf[2 * kb + 1]);
            *(u32*)(smp + HB_OFF + swz(r0, hcb + 4 * tig)) =
                packbf2(o[0] * inv0, o[1] * inv0);
            *(u32*)(smp + HB_OFF + swz(r1, hcb + 4 * tig)) =
                packbf2(o[2] * inv1, o[3] * inv1);
        }
    }
    PAIRBAR(strip);   // HB attn rows of this strip visible to the pair

    // ---- Wo GEMM; x1 = x + attn@Wo + bo (registers only) ----
    {
        float d[16] = {0};
        gemm64g(sb + HB_OFF, m0, wbase + 3 * 512, d);  // reads HB own strip rows
        #pragma unroll
        for (int nb = 0; nb < 4; nb++) {
            int col = nh * 32 + nb * 8 + tig * 2;
            float2 bv = *(const float2*)&bo[col];
            xv[nb * 4 + 0] += d[nb * 4 + 0] + bv.x;
            xv[nb * 4 + 1] += d[nb * 4 + 1] + bv.y;
            xv[nb * 4 + 2] += d[nb * 4 + 2] + bv.x;
            xv[nb * 4 + 3] += d[nb * 4 + 3] + bv.y;
        }
    }
    // LN2 -> HB (internal PAIRBAR orders the pair's Wo reads before overwrite)
    ln_frag(xv, smp + HB_OFF, lnp, g2, be2, m0, nh, l, strip);
    __syncthreads();  // FULL: LN2-HB visible + KB/VB WAR (attention done everywhere)

    // ---- FFN: HB A-frags loaded once; relu double-buffered KB/VB; pair bars ----
    float dff[16] = {0};
    {
        u32 af2[4][4];
        load_afrags(sb + HB_OFF, m0, af2);  // own strip rows
        #pragma unroll
        for (int c = 0; c < 4; c++) {
            const u32 rbo = (c & 1) ? (u32)VB_OFF : (u32)KB_OFF;
            {
                float d[16] = {0};
                gemm64_frag(af2, wbase + (4 + c) * 512, d);
                #pragma unroll
                for (int nb = 0; nb < 4; nb++) {
                    int col = nh * 32 + nb * 8 + tig * 2;
                    float2 bv = *(const float2*)&b1[c * 64 + col];
                    u32 p0 = packbf2(fmaxf(d[nb * 4 + 0] + bv.x, 0.f),
                                     fmaxf(d[nb * 4 + 1] + bv.y, 0.f));
                    u32 p1 = packbf2(fmaxf(d[nb * 4 + 2] + bv.x, 0.f),
                                     fmaxf(d[nb * 4 + 3] + bv.y, 0.f));
                    *(u32*)(smp + rbo + swz(r0, col * 2)) = p0;
                    *(u32*)(smp + rbo + swz(r1, col * 2)) = p1;
                }
            }
            PAIRBAR(strip);  // relu strip rows (both col-halves) visible to pair
            gemm64g(sb + rbo, m0, wbase + (8 + c) * 512, dff);
            // WAR for buffer reuse at c+2 is same-strip; covered by the c+2
            // iteration's PAIRBAR ordering relative to this pair's reads? No —
            // need the pair's reads done before the pair re-writes: the next
            // write to THIS buffer happens at c+2 by the same pair, after the
            // c+1 PAIRBAR, which orders both warps past the c reads. Safe.
        }
    }

    // ---- out = x1 + ff + b2 (registers -> global) ----
    #pragma unroll
    for (int nb = 0; nb < 4; nb++) {
        int col = nh * 32 + nb * 8 + tig * 2;
        float2 bv = *(const float2*)&b2[col];
        float2 o0 = {xv[nb * 4 + 0] + dff[nb * 4 + 0] + bv.x,
                     xv[nb * 4 + 1] + dff[nb * 4 + 1] + bv.y};
        float2 o1 = {xv[nb * 4 + 2] + dff[nb * 4 + 2] + bv.x,
                     xv[nb * 4 + 3] + dff[nb * 4 + 3] + bv.y};
        *(float2*)&og[r0 * 64 + col] = o0;
        *(float2*)&og[r1 * 64 + col] = o1;
    }
}

extern "C" void kernel_launch(void* const* d_in, const int* in_sizes, int n_in,
                              void* d_out, int out_size) {
    (void)in_sizes; (void)n_in; (void)out_size;
    const float* x   = (const float*)d_in[0];
    const float* Wq  = (const float*)d_in[1];
    const float* Wk  = (const float*)d_in[2];
    const float* Wv  = (const float*)d_in[3];
    const float* Wo  = (const float*)d_in[4];
    const float* bo  = (const float*)d_in[5];
    const float* W1  = (const float*)d_in[6];
    const float* b1  = (const float*)d_in[7];
    const float* W2  = (const float*)d_in[8];
    const float* b2  = (const float*)d_in[9];
    const float* g1  = (const float*)d_in[10];
    const float* be1 = (const float*)d_in[11];
    const float* g2  = (const float*)d_in[12];
    const float* be2 = (const float*)d_in[13];
    float* out = (float*)d_out;

    prep_kernel<<<12, 256>>>(Wq, Wk, Wv, Wo, W1, W2);

    cudaFuncSetAttribute(block_kernel,
                         cudaFuncAttributeMaxDynamicSharedMemorySize, SMEM_BYTES);
    block_kernel<<<4096, 256, SMEM_BYTES>>>(x, bo, b1, b2, g1, be1, g2, be2, out);
}

// round 15
// speedup vs baseline: 1.0986x; 1.0494x over previous
#include <cuda_runtime.h>
#include <cuda_bf16.h>

typedef unsigned int u32;
typedef unsigned long long u64;

#define EPSV 1e-5f
// 0.125 * log2(e): q pre-scale so softmax exp becomes exp2 (MUFU.EX2)
#define QSCALE 0.18033688011112042f

// ---- smem (per CTA, 41984B) ----
#define HB_OFF  0        // 8KB: LN out / attn out / LN2 out (bf16 swizzled)
#define KB_OFF  8192     // 8KB: k bf16 (relu buffer c2 in FFN)
#define VB_OFF  16384    // 8KB: v bf16 (relu buffer c3 in FFN)
#define R2_OFF  24576    // 8KB: relu buffer c0
#define R3_OFF  32768    // 8KB: relu buffer c1
#define LNP_OFF 40960    // 1KB: LN partial sums
#define SMEM_BYTES 41984

// pair barrier: the two warps (strip, nh=0) and (strip, nh=1); 64 threads
#define PAIRBAR(s) asm volatile("bar.sync %0, 64;" :: "r"((s) + 1) : "memory")

// weights in MMA B-fragment order:
// [tile(12)][nh(2)][kk(4)][half(2)][lane(32)] x uint4
// tile: 0-2 Wq/Wk/Wv, 3 Wo, 4-7 W1 chunks, 8-11 W2 chunks
__device__ __align__(16) unsigned char g_wfrag[98304];

__device__ __forceinline__ u32 swz(int row, int colbytes) {
    return (u32)(row * 128) + ((u32)colbytes ^ (u32)((row & 7) << 4));
}

__device__ __forceinline__ u32 smem_u32(const void* p) {
    u32 a;
    asm("{ .reg .u64 t; cvta.to.shared.u64 t, %1; cvt.u32.u64 %0, t; }"
        : "=r"(a) : "l"(p));
    return a;
}

__device__ __forceinline__ void ldsm_x4(u32 addr, u32& r0, u32& r1, u32& r2, u32& r3) {
    asm volatile("ldmatrix.sync.aligned.m8n8.x4.shared.b16 {%0,%1,%2,%3}, [%4];"
                 : "=r"(r0), "=r"(r1), "=r"(r2), "=r"(r3) : "r"(addr));
}
__device__ __forceinline__ void ldsm_x4t(u32 addr, u32& r0, u32& r1, u32& r2, u32& r3) {
    asm volatile("ldmatrix.sync.aligned.m8n8.x4.trans.shared.b16 {%0,%1,%2,%3}, [%4];"
                 : "=r"(r0), "=r"(r1), "=r"(r2), "=r"(r3) : "r"(addr));
}
__device__ __forceinline__ void mma_bf16(float* d, u32 a0, u32 a1, u32 a2, u32 a3,
                                         u32 b0, u32 b1) {
    asm volatile(
        "mma.sync.aligned.m16n8k16.row.col.f32.bf16.bf16.f32 "
        "{%0,%1,%2,%3}, {%4,%5,%6,%7}, {%8,%9}, {%0,%1,%2,%3};"
        : "+f"(d[0]), "+f"(d[1]), "+f"(d[2]), "+f"(d[3])
        : "r"(a0), "r"(a1), "r"(a2), "r"(a3), "r"(b0), "r"(b1));
}
__device__ __forceinline__ void mma_bf16_k8(float* d, u32 a0, u32 a1, u32 b0) {
    asm volatile(
        "mma.sync.aligned.m16n8k8.row.col.f32.bf16.bf16.f32 "
        "{%0,%1,%2,%3}, {%4,%5}, {%6}, {%0,%1,%2,%3};"
        : "+f"(d[0]), "+f"(d[1]), "+f"(d[2]), "+f"(d[3])
        : "r"(a0), "r"(a1), "r"(b0));
}

__device__ __forceinline__ void load_afrags(u32 abase, int m0, u32 af[4][4]) {
    const int l = threadIdx.x & 31;
    const int ar = m0 + (l & 15);
    const u32 arow = abase + (u32)(ar * 128);
    const u32 axor = (u32)((ar & 7) << 4);
    const int acol = (l >> 4) * 8;
    #pragma unroll
    for (int kk = 0; kk < 4; kk++)
        ldsm_x4(arow + (((u32)((kk * 16 + acol) * 2)) ^ axor),
                af[kk][0], af[kk][1], af[kk][2], af[kk][3]);
}

// D[16x32] += A(frags) * B[64x64] (cols nh*32..+31); B frags via coalesced LDG (L1-hit)
__device__ __forceinline__ void gemm64_frag(const u32 af[4][4],
                                            const uint4* __restrict__ wf, float d[16]) {
    const int l = threadIdx.x & 31;
    #pragma unroll
    for (int kk = 0; kk < 4; kk++) {
        uint4 B0 = __ldg(&wf[kk * 64 + l]);
        uint4 B1 = __ldg(&wf[kk * 64 + 32 + l]);
        mma_bf16(d + 0, af[kk][0], af[kk][1], af[kk][2], af[kk][3], B0.x, B0.y);
        mma_bf16(d + 4, af[kk][0], af[kk][1], af[kk][2], af[kk][3], B0.z, B0.w);
        mma_bf16(d + 8, af[kk][0], af[kk][1], af[kk][2], af[kk][3], B1.x, B1.y);
        mma_bf16(d + 12, af[kk][0], af[kk][1], af[kk][2], af[kk][3], B1.z, B1.w);
    }
}

__device__ __forceinline__ void gemm64g(u32 abase, int m0,
                                        const uint4* __restrict__ wf, float d[16]) {
    u32 af[4][4];
    load_afrags(abase, m0, af);
    gemm64_frag(af, wf, d);
}

__device__ __forceinline__ u32 packbf2(float a, float b) {
    __nv_bfloat162 p = __float22bfloat162_rn(make_float2(a, b));
    return *(u32*)&p;
}

__device__ __forceinline__ void store_bf16_tile(unsigned char* t, int m0, int nh,
                                                const float d[16]) {
    const int l = threadIdx.x & 31;
    const int grp = l >> 2, tig = l & 3;
    const int r0 = m0 + grp, r1 = m0 + grp + 8;
    #pragma unroll
    for (int nb = 0; nb < 4; nb++) {
        int cb = (nh * 32 + nb * 8 + tig * 2) * 2;
        *(u32*)(t + swz(r0, cb)) = packbf2(d[nb * 4 + 0], d[nb * 4 + 1]);
        *(u32*)(t + swz(r1, cb)) = packbf2(d[nb * 4 + 2], d[nb * 4 + 3]);
    }
}

// fragment-layout LayerNorm: xv[16] -> bf16 HB tile.
// Internal PAIR barrier: the row sums only couple the two warps of one strip.
__device__ __forceinline__ void ln_frag(const float xv[16], unsigned char* hb,
                                        float* lnp, const float* g, const float* be,
                                        int m0, int nh, int l, int strip) {
    const int grp = l >> 2, tig = l & 3;
    const int r0 = m0 + grp, r1 = r0 + 8;
    float s0 = 0.f, ss0 = 0.f, s1 = 0.f, ss1 = 0.f;
    #pragma unroll
    for (int nb = 0; nb < 4; nb++) {
        s0 += xv[nb * 4 + 0] + xv[nb * 4 + 1];
        ss0 += xv[nb * 4 + 0] * xv[nb * 4 + 0] + xv[nb * 4 + 1] * xv[nb * 4 + 1];
        s1 += xv[nb * 4 + 2] + xv[nb * 4 + 3];
        ss1 += xv[nb * 4 + 2] * xv[nb * 4 + 2] + xv[nb * 4 + 3] * xv[nb * 4 + 3];
    }
    s0 += __shfl_xor_sync(0xffffffffu, s0, 1);
    s0 += __shfl_xor_sync(0xffffffffu, s0, 2);
    ss0 += __shfl_xor_sync(0xffffffffu, ss0, 1);
    ss0 += __shfl_xor_sync(0xffffffffu, ss0, 2);
    s1 += __shfl_xor_sync(0xffffffffu, s1, 1);
    s1 += __shfl_xor_sync(0xffffffffu, s1, 2);
    ss1 += __shfl_xor_sync(0xffffffffu, ss1, 1);
    ss1 += __shfl_xor_sync(0xffffffffu, ss1, 2);
    if (tig == 0) {
        *(float2*)&lnp[(nh * 64 + r0) * 2] = make_float2(s0, ss0);
        *(float2*)&lnp[(nh * 64 + r1) * 2] = make_float2(s1, ss1);
    }
    PAIRBAR(strip);
    float2 p0 = *(float2*)&lnp[((1 - nh) * 64 + r0) * 2];
    float2 p1 = *(float2*)&lnp[((1 - nh) * 64 + r1) * 2];
    float S0 = s0 + p0.x, Q0 = ss0 + p0.y;
    float S1 = s1 + p1.x, Q1 = ss1 + p1.y;
    float mu0 = S0 * (1.0f / 64.0f);
    float rs0 = rsqrtf(Q0 * (1.0f / 64.0f) - mu0 * mu0 + EPSV);
    float mu1 = S1 * (1.0f / 64.0f);
    float rs1 = rsqrtf(Q1 * (1.0f / 64.0f) - mu1 * mu1 + EPSV);
    #pragma unroll
    for (int nb = 0; nb < 4; nb++) {
        int col = nh * 32 + nb * 8 + tig * 2;
        float2 gv = *(const float2*)&g[col];
        float2 bv = *(const float2*)&be[col];
        float a0 = (xv[nb * 4 + 0] - mu0) * rs0 * gv.x + bv.x;
        float a1 = (xv[nb * 4 + 1] - mu0) * rs0 * gv.y + bv.y;
        float c0 = (xv[nb * 4 + 2] - mu1) * rs1 * gv.x + bv.x;
        float c1 = (xv[nb * 4 + 3] - mu1) * rs1 * gv.y + bv.y;
        *(u32*)(hb + swz(r0, col * 2)) = packbf2(a0, a1);
        *(u32*)(hb + swz(r1, col * 2)) = packbf2(c0, c1);
    }
}

// ---------------- prep: weights -> bf16 B-fragment order ----------------
__device__ __forceinline__ float w_fetch(int tile, int k, int n,
                                         const float* Wq, const float* Wk,
                                         const float* Wv, const float* Wo,
                                         const float* W1, const float* W2) {
    if (tile < 3) {
        const float* s = (tile == 0) ? Wq : (tile == 1) ? Wk : Wv;
        return s[k * 64 + n];
    } else if (tile == 3) {
        return Wo[k * 64 + n];
    } else if (tile < 8) {
        return W1[k * 256 + (tile - 4) * 64 + n];
    }
    return W2[((tile - 8) * 64 + k) * 64 + n];
}

__global__ void prep_kernel(const float* __restrict__ Wq, const float* __restrict__ Wk,
                            const float* __restrict__ Wv, const float* __restrict__ Wo,
                            const float* __restrict__ W1, const float* __restrict__ W2) {
    const int tile = blockIdx.x;
    for (int idx = threadIdx.x; idx < 2048; idx += 256) {
        int nh = idx >> 10;
        int rem = idx & 1023;
        int kk = rem >> 8;
        int rem2 = rem & 255;
        int half = rem2 >> 7;
        int rem3 = rem2 & 127;
        int lane = rem3 >> 2, i = rem3 & 3;
        int nblk = half * 2 + (i >> 1), hi = i & 1;
        int k = kk * 16 + (lane & 3) * 2 + hi * 8;
        int n = nh * 32 + nblk * 8 + (lane >> 2);
        float v0 = w_fetch(tile, k, n, Wq, Wk, Wv, Wo, W1, W2);
        float v1 = w_fetch(tile, k + 1, n, Wq, Wk, Wv, Wo, W1, W2);
        __nv_bfloat162 p = __float22bfloat162_rn(make_float2(v0, v1));
        *(u32*)(g_wfrag + tile * 8192 + nh * 4096 + kk * 1024 + half * 512 +
                lane * 16 + i * 4) = *(u32*)&p;
    }
}

__global__ void __launch_bounds__(256, 3)
block_kernel(const float* __restrict__ x,
             const float* __restrict__ bo,
             const float* __restrict__ b1, const float* __restrict__ b2,
             const float* __restrict__ g1, const float* __restrict__ be1,
             const float* __restrict__ g2, const float* __restrict__ be2,
             float* __restrict__ out) {
    extern __shared__ __align__(128) unsigned char smp[];
    float* lnp = (float*)(smp + LNP_OFF);
    const u32 sb = smem_u32(smp);

    const int tid = threadIdx.x;
    const int w = tid >> 5, l = tid & 31;
    const float* xg = x + (size_t)blockIdx.x * 4096;
    float* og = out + (size_t)blockIdx.x * 4096;

    const int strip = w & 3;       // 16-row strip index
    const int m0 = strip * 16;
    const int nh = w >> 2;         // 32-col half (0/1) == head-group
    const int grp = l >> 2, tig = l & 3;
    const int r0 = m0 + grp, r1 = r0 + 8;
    const uint4* wbase = (const uint4*)(g_wfrag + nh * 4096);

    // ---- load x residual (kept live all kernel); LN1 -> HB ----
    float xv[16];
    #pragma unroll
    for (int nb = 0; nb < 4; nb++) {
        int col = nh * 32 + nb * 8 + tig * 2;
        float2 t0 = *(const float2*)&xg[r0 * 64 + col];
        float2 t1 = *(const float2*)&xg[r1 * 64 + col];
        xv[nb * 4 + 0] = t0.x; xv[nb * 4 + 1] = t0.y;
        xv[nb * 4 + 2] = t1.x; xv[nb * 4 + 3] = t1.y;
    }
    ln_frag(xv, smp + HB_OFF, lnp, g1, be1, m0, nh, l, strip);
    PAIRBAR(strip);   // HB strip rows visible to the pair

    // ---- QKV: q kept in registers as m16k8 A-frags (exp2-prescaled); k/v -> smem ----
    u32 qa[4][2];
    {
        u32 af[4][4];
        load_afrags(sb + HB_OFF, m0, af);  // reads HB rows of own strip only
        {
            float d[16] = {0};
            gemm64_frag(af, wbase + 0 * 512, d);
            #pragma unroll
            for (int j = 0; j < 4; j++) {
                qa[j][0] = packbf2(d[j * 4 + 0] * QSCALE, d[j * 4 + 1] * QSCALE);
                qa[j][1] = packbf2(d[j * 4 + 2] * QSCALE, d[j * 4 + 3] * QSCALE);
            }
        }
        {
            float d[16] = {0};
            gemm64_frag(af, wbase + 1 * 512, d);
            store_bf16_tile(smp + KB_OFF, m0, nh, d);
        }
        {
            float d[16] = {0};
            gemm64_frag(af, wbase + 2 * 512, d);
            store_bf16_tile(smp + VB_OFF, m0, nh, d);
        }
    }
    __syncthreads();  // FULL: attention reads K/V rows from ALL strips

    // ---- attention (causal-block-skipped): warp = strip x heads nh*4..+3 ----
    {
        #pragma unroll
        for (int j = 0; j < 4; j++) {
            const int hcb = (nh * 4 + j) * 16;
            u32 kf[8], vf[8];
            ldsm_x4(sb + KB_OFF + swz(l, hcb), kf[0], kf[1], kf[2], kf[3]);
            ldsm_x4t(sb + VB_OFF + swz(l, hcb), vf[0], vf[1], vf[2], vf[3]);
            if (strip >= 2) {
                ldsm_x4(sb + KB_OFF + swz(32 + l, hcb), kf[4], kf[5], kf[6], kf[7]);
                ldsm_x4t(sb + VB_OFF + swz(32 + l, hcb), vf[4], vf[5], vf[6], vf[7]);
            }

            u32 pa[8], pb[8];
            float sum0 = 0.f, sum1 = 0.f;
            #pragma unroll
            for (int nb = 0; nb < 8; nb++) {
                if (nb >= 2 * strip + 2) continue;  // fully-masked block: skip
                float sacc[4] = {0.f, 0.f, 0.f, 0.f};
                mma_bf16_k8(sacc, qa[j][0], qa[j][1], kf[nb]);
                float e0, e1, e2, e3;
                if (nb < 2 * strip) {               // fully-unmasked: no compares
                    e0 = exp2f(sacc[0]); e1 = exp2f(sacc[1]);
                    e2 = exp2f(sacc[2]); e3 = exp2f(sacc[3]);
                } else {                            // boundary block
                    const int c0 = nb * 8 + 2 * tig;
                    e0 = (c0     <= r0    ) ? exp2f(sacc[0]) : 0.f;
                    e1 = (c0 + 1 <= r0    ) ? exp2f(sacc[1]) : 0.f;
                    e2 = (c0     <= r0 + 8) ? exp2f(sacc[2]) : 0.f;
                    e3 = (c0 + 1 <= r0 + 8) ? exp2f(sacc[3]) : 0.f;
                }
                sum0 += e0 + e1;
                sum1 += e2 + e3;
                pa[nb] = packbf2(e0, e1);
                pb[nb] = packbf2(e2, e3);
            }
            sum0 += __shfl_xor_sync(0xffffffffu, sum0, 1);
            sum0 += __shfl_xor_sync(0xffffffffu, sum0, 2);
            sum1 += __shfl_xor_sync(0xffffffffu, sum1, 1);
            sum1 += __shfl_xor_sync(0xffffffffu, sum1, 2);
            const float inv0 = 1.0f / sum0, inv1 = 1.0f / sum1;

            float o[4] = {0.f, 0.f, 0.f, 0.f};
            #pragma unroll
            for (int kb = 0; kb < 4; kb++)
                if (kb <= strip)
                    mma_bf16(o, pa[2 * kb], pb[2 * kb], pa[2 * kb + 1], pb[2 * kb + 1],
                             vf[2 * kb], vf[2 * kb + 1]);
            *(u32*)(smp + HB_OFF + swz(r0, hcb + 4 * tig)) =
                packbf2(o[0] * inv0, o[1] * inv0);
            *(u32*)(smp + HB_OFF + swz(r1, hcb + 4 * tig)) =
                packbf2(o[2] * inv1, o[3] * inv1);
        }
    }
    PAIRBAR(strip);   // HB attn rows of this strip visible to the pair

    // ---- Wo GEMM; x1 = x + attn@Wo + bo (registers only) ----
    {
        float d[16] = {0};
        gemm64g(sb + HB_OFF, m0, wbase + 3 * 512, d);  // reads HB own strip rows
        #pragma unroll
        for (int nb = 0; nb < 4; nb++) {
            int col = nh * 32 + nb * 8 + tig * 2;
            float2 bv = *(const float2*)&bo[col];
            xv[nb * 4 + 0] += d[nb * 4 + 0] + bv.x;
            xv[nb * 4 + 1] += d[nb * 4 + 1] + bv.y;
            xv[nb * 4 + 2] += d[nb * 4 + 2] + bv.x;
            xv[nb * 4 + 3] += d[nb * 4 + 3] + bv.y;
        }
    }
    // LN2 -> HB (internal PAIRBAR orders the pair's Wo reads before overwrite)
    ln_frag(xv, smp + HB_OFF, lnp, g2, be2, m0, nh, l, strip);
    PAIRBAR(strip);   // LN2-HB strip rows visible to the pair

    // ---- FFN: FF1 all chunks first (c0,c1 -> fresh R2/R3; full sync; c2,c3 -> KB/VB),
    //      then FF2 all chunks back-to-back with no barriers ----
    float dff[16] = {0};
    {
        u32 af2[4][4];
        load_afrags(sb + HB_OFF, m0, af2);  // own strip rows
        const u32 rbuf[4] = {R2_OFF, R3_OFF, KB_OFF, VB_OFF};

        #pragma unroll
        for (int c = 0; c < 4; c++) {
            if (c == 2) __syncthreads();  // FULL: all attention K/V reads done
                                          // before KB/VB are overwritten
            float d[16] = {0};
            gemm64_frag(af2, wbase + (4 + c) * 512, d);
            #pragma unroll
            for (int nb = 0; nb < 4; nb++) {
                int col = nh * 32 + nb * 8 + tig * 2;
                float2 bv = *(const float2*)&b1[c * 64 + col];
                u32 p0 = packbf2(fmaxf(d[nb * 4 + 0] + bv.x, 0.f),
                                 fmaxf(d[nb * 4 + 1] + bv.y, 0.f));
                u32 p1 = packbf2(fmaxf(d[nb * 4 + 2] + bv.x, 0.f),
                                 fmaxf(d[nb * 4 + 3] + bv.y, 0.f));
                *(u32*)(smp + rbuf[c] + swz(r0, col * 2)) = p0;
                *(u32*)(smp + rbuf[c] + swz(r1, col * 2)) = p1;
            }
        }
        PAIRBAR(strip);  // all 4 relu buffers' strip rows visible to the pair

        #pragma unroll
        for (int c = 0; c < 4; c++)
            gemm64g(sb + rbuf[c], m0, wbase + (8 + c) * 512, dff);
    }

    // ---- out = x1 + ff + b2 (registers -> global) ----
    #pragma unroll
    for (int nb = 0; nb < 4; nb++) {
        int col = nh * 32 + nb * 8 + tig * 2;
        float2 bv = *(const float2*)&b2[col];
        float2 o0 = {xv[nb * 4 + 0] + dff[nb * 4 + 0] + bv.x,
                     xv[nb * 4 + 1] + dff[nb * 4 + 1] + bv.y};
        float2 o1 = {xv[nb * 4 + 2] + dff[nb * 4 + 2] + bv.x,
                     xv[nb * 4 + 3] + dff[nb * 4 + 3] + bv.y};
        *(float2*)&og[r0 * 64 + col] = o0;
        *(float2*)&og[r1 * 64 + col] = o1;
    }
}

extern "C" void kernel_launch(void* const* d_in, const int* in_sizes, int n_in,
                              void* d_out, int out_size) {
    (void)in_sizes; (void)n_in; (void)out_size;
    const float* x   = (const float*)d_in[0];
    const float* Wq  = (const float*)d_in[1];
    const float* Wk  = (const float*)d_in[2];
    const float* Wv  = (const float*)d_in[3];
    const float* Wo  = (const float*)d_in[4];
    const float* bo  = (const float*)d_in[5];
    const float* W1  = (const float*)d_in[6];
    const float* b1  = (const float*)d_in[7];
    const float* W2  = (const float*)d_in[8];
    const float* b2  = (const float*)d_in[9];
    const float* g1  = (const float*)d_in[10];
    const float* be1 = (const float*)d_in[11];
    const float* g2  = (const float*)d_in[12];
    const float* be2 = (const float*)d_in[13];
    float* out = (float*)d_out;

    prep_kernel<<<12, 256>>>(Wq, Wk, Wv, Wo, W1, W2);

    cudaFuncSetAttribute(block_kernel,
                         cudaFuncAttributeMaxDynamicSharedMemorySize, SMEM_BYTES);
    block_kernel<<<4096, 256, SMEM_BYTES>>>(x, bo, b1, b2, g1, be1, g2, be2, out);
}